// round 1
// baseline (speedup 1.0000x reference)
#include <cuda_runtime.h>
#include <cuda_bf16.h>
#include <math.h>

// ---------------- problem constants ----------------
#define NT      16384      // tokens = 4*4096
#define HID     4096
#define NE      64         // experts
#define TOPK    2
#define NK      (NT*TOPK)  // 32768

// output layout (concatenated f32, in reference return order)
#define OFF_W      0
#define OFF_IDX    (NK)            // 32768
#define OFF_OFFS   (2*NK)          // 65536
#define OFF_GATHER (2*NK + NE)     // 65600
#define OFF_AUX    (3*NK + NE)     // 98368
#define OFF_Z      (3*NK + NE + 1) // 98369

// GEMM tiling
#define BM   64
#define BK   32
#define LDA  68   // padded row stride (floats) for smem tiles
#define LDL  65   // padded row stride for logits

// ---------------- device scratch (no allocs allowed) ----------------
__device__ int g_flat[NK];     // flat expert ids, token-major
__device__ int g_counts[NE];
__device__ int g_offsets[NE];  // exclusive offsets

// ===================================================================
// Kernel 1: fused router GEMM + softmax + top2 + normalize
// grid = NT/BM = 256 blocks, 256 threads
// thread (ty,tx): ty in [0,16) -> 4 tokens, tx in [0,16) -> 4 experts
// ===================================================================
__global__ __launch_bounds__(256) void router_kernel(
    const float* __restrict__ x,   // [NT, HID]
    const float* __restrict__ w,   // [NE, HID]
    float* __restrict__ out)
{
    __shared__ float sA[BK * LDA];   // [k][token]
    __shared__ float sB[BK * LDA];   // [k][expert]
    __shared__ float lsm[BM * LDL];  // logits [token][expert]

    const int tid = threadIdx.x;
    const int tx  = tid & 15;
    const int ty  = tid >> 4;
    const int row0 = blockIdx.x * BM;

    const float4* x4 = (const float4*)x;
    const float4* w4 = (const float4*)w;
    const int H4 = HID / 4;

    // load mapping: 512 float4 per tile, 2 per thread
    const int u0 = tid;
    const int u1 = tid + 256;
    const int ra0 = u0 >> 3, ca0 = u0 & 7;
    const int ra1 = u1 >> 3, ca1 = u1 & 7;

    float acc[4][4];
#pragma unroll
    for (int i = 0; i < 4; i++)
#pragma unroll
        for (int j = 0; j < 4; j++) acc[i][j] = 0.f;

    // prefetch tile 0 into registers
    float4 pa0 = x4[(row0 + ra0) * H4 + ca0];
    float4 pa1 = x4[(row0 + ra1) * H4 + ca1];
    float4 pb0 = w4[ra0 * H4 + ca0];
    float4 pb1 = w4[ra1 * H4 + ca1];

    const int NTILE = HID / BK;  // 128
    for (int kt = 0; kt < NTILE; ++kt) {
        // commit prefetched tile to smem (transposed: [k][m])
        sA[(ca0*4+0)*LDA + ra0] = pa0.x;
        sA[(ca0*4+1)*LDA + ra0] = pa0.y;
        sA[(ca0*4+2)*LDA + ra0] = pa0.z;
        sA[(ca0*4+3)*LDA + ra0] = pa0.w;
        sA[(ca1*4+0)*LDA + ra1] = pa1.x;
        sA[(ca1*4+1)*LDA + ra1] = pa1.y;
        sA[(ca1*4+2)*LDA + ra1] = pa1.z;
        sA[(ca1*4+3)*LDA + ra1] = pa1.w;

        sB[(ca0*4+0)*LDA + ra0] = pb0.x;
        sB[(ca0*4+1)*LDA + ra0] = pb0.y;
        sB[(ca0*4+2)*LDA + ra0] = pb0.z;
        sB[(ca0*4+3)*LDA + ra0] = pb0.w;
        sB[(ca1*4+0)*LDA + ra1] = pb1.x;
        sB[(ca1*4+1)*LDA + ra1] = pb1.y;
        sB[(ca1*4+2)*LDA + ra1] = pb1.z;
        sB[(ca1*4+3)*LDA + ra1] = pb1.w;
        __syncthreads();

        // prefetch next tile (overlaps with compute below)
        if (kt + 1 < NTILE) {
            int kb = (kt + 1) * (BK / 4);
            pa0 = x4[(row0 + ra0) * H4 + kb + ca0];
            pa1 = x4[(row0 + ra1) * H4 + kb + ca1];
            pb0 = w4[ra0 * H4 + kb + ca0];
            pb1 = w4[ra1 * H4 + kb + ca1];
        }

#pragma unroll
        for (int k = 0; k < BK; ++k) {
            float4 a = *(const float4*)&sA[k * LDA + ty * 4];
            float4 b = *(const float4*)&sB[k * LDA + tx * 4];
            acc[0][0] = fmaf(a.x, b.x, acc[0][0]);
            acc[0][1] = fmaf(a.x, b.y, acc[0][1]);
            acc[0][2] = fmaf(a.x, b.z, acc[0][2]);
            acc[0][3] = fmaf(a.x, b.w, acc[0][3]);
            acc[1][0] = fmaf(a.y, b.x, acc[1][0]);
            acc[1][1] = fmaf(a.y, b.y, acc[1][1]);
            acc[1][2] = fmaf(a.y, b.z, acc[1][2]);
            acc[1][3] = fmaf(a.y, b.w, acc[1][3]);
            acc[2][0] = fmaf(a.z, b.x, acc[2][0]);
            acc[2][1] = fmaf(a.z, b.y, acc[2][1]);
            acc[2][2] = fmaf(a.z, b.z, acc[2][2]);
            acc[2][3] = fmaf(a.z, b.w, acc[2][3]);
            acc[3][0] = fmaf(a.w, b.x, acc[3][0]);
            acc[3][1] = fmaf(a.w, b.y, acc[3][1]);
            acc[3][2] = fmaf(a.w, b.z, acc[3][2]);
            acc[3][3] = fmaf(a.w, b.w, acc[3][3]);
        }
        __syncthreads();
    }

    // stage logits to smem
#pragma unroll
    for (int i = 0; i < 4; i++)
#pragma unroll
        for (int j = 0; j < 4; j++)
            lsm[(ty*4 + i) * LDL + tx*4 + j] = acc[i][j];
    __syncthreads();

    // one thread per token: softmax + top2 + normalize
    if (tid < BM) {
        const float* l = &lsm[tid * LDL];
        float mx = -3.0e38f;
#pragma unroll
        for (int e = 0; e < NE; ++e) mx = fmaxf(mx, l[e]);
        float Z = 0.f;
#pragma unroll
        for (int e = 0; e < NE; ++e) Z += expf(l[e] - mx);

        float m1 = -3.0e38f, m2 = -3.0e38f;
        int i1 = 0, i2 = 0;
        for (int e = 0; e < NE; ++e) {
            float v = l[e];
            if (v > m1) { m2 = m1; i2 = i1; m1 = v; i1 = e; }
            else if (v > m2) { m2 = v; i2 = e; }
        }
        float p1 = expf(m1 - mx) / Z;
        float p2 = expf(m2 - mx) / Z;
        float s = p1 + p2 + 1e-8f;

        int n = row0 + tid;
        out[OFF_W + 2*n]     = p1 / s;
        out[OFF_W + 2*n + 1] = p2 / s;
        out[OFF_IDX + 2*n]     = (float)i1;
        out[OFF_IDX + 2*n + 1] = (float)i2;
        g_flat[2*n]     = i1;
        g_flat[2*n + 1] = i2;
    }
}

// ===================================================================
// Kernel 2: zero counts
// ===================================================================
__global__ void zero_kernel() {
    if (threadIdx.x < NE) g_counts[threadIdx.x] = 0;
}

// ===================================================================
// Kernel 3: histogram (smem-aggregated)
// ===================================================================
__global__ void hist_kernel() {
    __shared__ int h[NE];
    if (threadIdx.x < NE) h[threadIdx.x] = 0;
    __syncthreads();
    for (int i = blockIdx.x * blockDim.x + threadIdx.x; i < NK;
         i += gridDim.x * blockDim.x)
        atomicAdd(&h[g_flat[i]], 1);
    __syncthreads();
    if (threadIdx.x < NE) atomicAdd(&g_counts[threadIdx.x], h[threadIdx.x]);
}

// ===================================================================
// Kernel 4: cumsum -> expert_offsets (inclusive) + exclusive to scratch
//           also write aux/z losses
// ===================================================================
__global__ void scan_kernel(float* __restrict__ out) {
    if (threadIdx.x == 0) {
        int s = 0;
        for (int e = 0; e < NE; ++e) {
            int c = g_counts[e];
            g_offsets[e] = s;
            s += c;
            out[OFF_OFFS + e] = (float)s;
        }
        out[OFF_AUX] = 0.f;
        out[OFF_Z]   = 0.f;
    }
}

// ===================================================================
// Kernel 5: stable counting sort -> gather_indices
// one block per expert; block-wide ballot scan preserves order
// ===================================================================
__global__ __launch_bounds__(256) void rank_kernel(float* __restrict__ out) {
    const int e = blockIdx.x;
    __shared__ int warp_tot[8];
    const int tid = threadIdx.x;
    const int lane = tid & 31;
    const int wid = tid >> 5;
    int base = g_offsets[e];

    for (int start = 0; start < NK; start += 256) {
        int i = start + tid;
        int flag = (g_flat[i] == e) ? 1 : 0;
        unsigned m = __ballot_sync(0xffffffffu, flag);
        int wprefix = __popc(m & ((1u << lane) - 1u));
        if (lane == 0) warp_tot[wid] = __popc(m);
        __syncthreads();
        int woff = 0, tot = 0;
#pragma unroll
        for (int wd = 0; wd < 8; ++wd) {
            int t = warp_tot[wd];
            if (wd < wid) woff += t;
            tot += t;
        }
        if (flag) out[OFF_GATHER + base + woff + wprefix] = (float)i;
        base += tot;
        __syncthreads();
    }
}

// ===================================================================
extern "C" void kernel_launch(void* const* d_in, const int* in_sizes, int n_in,
                              void* d_out, int out_size)
{
    const float* x = (const float*)d_in[0];  // hidden_states [4,4096,4096]
    const float* w = (const float*)d_in[1];  // gate_w [64,4096]
    float* out = (float*)d_out;

    zero_kernel<<<1, 64>>>();
    router_kernel<<<NT / BM, 256>>>(x, w, out);
    hist_kernel<<<64, 256>>>();
    scan_kernel<<<1, 32>>>(out);
    rank_kernel<<<NE, 256>>>(out);
}

// round 3
// speedup vs baseline: 2.5221x; 2.5221x over previous
#include <cuda_runtime.h>
#include <cuda_bf16.h>
#include <cstdint>
#include <math.h>

// ---------------- problem constants ----------------
#define NT      16384
#define HID     4096
#define NE      64
#define NK      32768

#define OFF_W      0
#define OFF_IDX    32768
#define OFF_OFFS   65536
#define OFF_GATHER 65600
#define OFF_AUX    98368
#define OFF_Z      98369

// GEMM tiling
#define MTILE   128
#define KC      64                  // bf16 K per chunk
#define NCHUNK  (HID / KC)          // 64
#define NCTA    (NT / MTILE)        // 128

// smem: padded rows, 64 bf16 + 8 pad = 72 bf16 = 144 bytes
#define RSTRIDE 144
#define A_BYTES (MTILE * RSTRIDE)   // 18432
#define B_BYTES (NE * RSTRIDE)      // 9216
#define SM_AHI  0
#define SM_ALO  (A_BYTES)
#define SM_BHI  (2 * A_BYTES)
#define SM_BLO  (2 * A_BYTES + B_BYTES)
#define SM_TOTAL (2 * A_BYTES + 2 * B_BYTES)   // 55296
#define LDL     65                  // logits smem stride (floats), overlays A region

// ---------------- device scratch ----------------
__device__ int g_flat[NK];
__device__ int g_bc[NE * NCTA];
__device__ int g_off2[NE * NCTA];
__device__ __align__(16) __nv_bfloat16 g_whi[NE * HID];
__device__ __align__(16) __nv_bfloat16 g_wlo[NE * HID];

__device__ __forceinline__ unsigned pack_bf2(__nv_bfloat16 a, __nv_bfloat16 b) {
    return (unsigned)__bfloat16_as_ushort(a) | ((unsigned)__bfloat16_as_ushort(b) << 16);
}

__device__ __forceinline__ void mma16816(float* d, const uint32_t* a, const uint32_t* b) {
    asm volatile(
        "mma.sync.aligned.m16n8k16.row.col.f32.bf16.bf16.f32 "
        "{%0,%1,%2,%3}, {%4,%5,%6,%7}, {%8,%9}, {%0,%1,%2,%3};"
        : "+f"(d[0]), "+f"(d[1]), "+f"(d[2]), "+f"(d[3])
        : "r"(a[0]), "r"(a[1]), "r"(a[2]), "r"(a[3]), "r"(b[0]), "r"(b[1]));
}

// ===================================================================
// Kernel 0: preconvert gate_w to bf16 hi/lo
// ===================================================================
__global__ __launch_bounds__(256) void wconv_kernel(const float* __restrict__ w) {
    int i = blockIdx.x * 256 + threadIdx.x;
    float v = w[i];
    __nv_bfloat16 h = __float2bfloat16_rn(v);
    g_whi[i] = h;
    g_wlo[i] = __float2bfloat16_rn(v - __bfloat162float(h));
}

// ===================================================================
// Kernel 1: HMMA router GEMM (bf16 split) + softmax + top2 + hist
// grid = 128 CTAs x 256 threads (8 warps: 4 M-rows x 2 N-cols)
// ===================================================================
__global__ __launch_bounds__(256, 1) void router_kernel(
    const float* __restrict__ x, float* __restrict__ out)
{
    extern __shared__ __align__(16) char smem[];
    const int tid  = threadIdx.x;
    const int wid  = tid >> 5;
    const int lane = tid & 31;
    const int row0 = blockIdx.x * MTILE;

    const int wrow = wid >> 1;          // 0..3 -> 32-token group
    const int wcol = wid & 1;           // 0..1 -> 32-expert group
    const int g = lane >> 2;            // 0..7
    const int q = lane & 3;             // 0..3

    // ---- gmem load mappings ----
    // A: 128 rows x 16 float4 per chunk = 2048 units, 8 per thread
    const float4* x4 = (const float4*)x;
    int a_r[8], a_c4[8];
#pragma unroll
    for (int i = 0; i < 8; i++) {
        int u = tid + 256 * i;
        a_r[i]  = u >> 4;
        a_c4[i] = u & 15;
    }
    // B: 64 rows x 8 float4 (8 bf16) per split per chunk = 512 units, 2/thread
    int b_r[2], b_c16[2];
#pragma unroll
    for (int j = 0; j < 2; j++) {
        int u = tid + 256 * j;
        b_r[j]   = u >> 3;
        b_c16[j] = u & 7;
    }
    const float4* whi4 = (const float4*)g_whi;
    const float4* wlo4 = (const float4*)g_wlo;

    // prefetch chunk 0
    float4 pa[8], pbh[2], pbl[2];
#pragma unroll
    for (int i = 0; i < 8; i++)
        pa[i] = x4[(size_t)(row0 + a_r[i]) * (HID / 4) + a_c4[i]];
#pragma unroll
    for (int j = 0; j < 2; j++) {
        int gi = b_r[j] * (HID / 8) + b_c16[j];
        pbh[j] = whi4[gi];
        pbl[j] = wlo4[gi];
    }

    float acc[2][4][4];
#pragma unroll
    for (int mi = 0; mi < 2; mi++)
#pragma unroll
        for (int ni = 0; ni < 4; ni++)
#pragma unroll
            for (int c = 0; c < 4; c++) acc[mi][ni][c] = 0.f;

#pragma unroll 1
    for (int s = 0; s < NCHUNK; ++s) {
        // ---- commit prefetched chunk to smem (convert A fp32 -> hi/lo) ----
#pragma unroll
        for (int i = 0; i < 8; i++) {
            float4 v = pa[i];
            __nv_bfloat16 hx = __float2bfloat16_rn(v.x);
            __nv_bfloat16 hy = __float2bfloat16_rn(v.y);
            __nv_bfloat16 hz = __float2bfloat16_rn(v.z);
            __nv_bfloat16 hw = __float2bfloat16_rn(v.w);
            uint2 H, L;
            H.x = pack_bf2(hx, hy);
            H.y = pack_bf2(hz, hw);
            L.x = pack_bf2(__float2bfloat16_rn(v.x - __bfloat162float(hx)),
                           __float2bfloat16_rn(v.y - __bfloat162float(hy)));
            L.y = pack_bf2(__float2bfloat16_rn(v.z - __bfloat162float(hz)),
                           __float2bfloat16_rn(v.w - __bfloat162float(hw)));
            int off = a_r[i] * RSTRIDE + a_c4[i] * 8;
            *(uint2*)(smem + SM_AHI + off) = H;
            *(uint2*)(smem + SM_ALO + off) = L;
        }
#pragma unroll
        for (int j = 0; j < 2; j++) {
            int off = b_r[j] * RSTRIDE + b_c16[j] * 16;
            *(float4*)(smem + SM_BHI + off) = pbh[j];
            *(float4*)(smem + SM_BLO + off) = pbl[j];
        }
        __syncthreads();

        // ---- prefetch next chunk (overlaps compute) ----
        if (s + 1 < NCHUNK) {
            const int ka = (s + 1) * (KC / 4);
            const int kb = (s + 1) * (KC / 8);
#pragma unroll
            for (int i = 0; i < 8; i++)
                pa[i] = x4[(size_t)(row0 + a_r[i]) * (HID / 4) + ka + a_c4[i]];
#pragma unroll
            for (int j = 0; j < 2; j++) {
                int gi = b_r[j] * (HID / 8) + kb + b_c16[j];
                pbh[j] = whi4[gi];
                pbl[j] = wlo4[gi];
            }
        }

        // ---- compute: 4 k-steps of 16 ----
#pragma unroll
        for (int ks = 0; ks < 4; ++ks) {
            const int k0 = ks * 16 + q * 2;          // bf16 col of pair
            uint32_t Ah[2][4], Al[2][4], Bh[4][2], Bl[4][2];
#pragma unroll
            for (int mi = 0; mi < 2; mi++) {
                int r = wrow * 32 + mi * 16 + g;
                int o00 = r * RSTRIDE + k0 * 2;
                int o10 = (r + 8) * RSTRIDE + k0 * 2;
                Ah[mi][0] = *(const uint32_t*)(smem + SM_AHI + o00);
                Ah[mi][1] = *(const uint32_t*)(smem + SM_AHI + o10);
                Ah[mi][2] = *(const uint32_t*)(smem + SM_AHI + o00 + 16);
                Ah[mi][3] = *(const uint32_t*)(smem + SM_AHI + o10 + 16);
                Al[mi][0] = *(const uint32_t*)(smem + SM_ALO + o00);
                Al[mi][1] = *(const uint32_t*)(smem + SM_ALO + o10);
                Al[mi][2] = *(const uint32_t*)(smem + SM_ALO + o00 + 16);
                Al[mi][3] = *(const uint32_t*)(smem + SM_ALO + o10 + 16);
            }
#pragma unroll
            for (int ni = 0; ni < 4; ni++) {
                int n = wcol * 32 + ni * 8 + g;
                int o = n * RSTRIDE + k0 * 2;
                Bh[ni][0] = *(const uint32_t*)(smem + SM_BHI + o);
                Bh[ni][1] = *(const uint32_t*)(smem + SM_BHI + o + 16);
                Bl[ni][0] = *(const uint32_t*)(smem + SM_BLO + o);
                Bl[ni][1] = *(const uint32_t*)(smem + SM_BLO + o + 16);
            }
#pragma unroll
            for (int mi = 0; mi < 2; mi++)
#pragma unroll
                for (int ni = 0; ni < 4; ni++) {
                    mma16816(acc[mi][ni], Ah[mi], Bh[ni]);
                    mma16816(acc[mi][ni], Ah[mi], Bl[ni]);
                    mma16816(acc[mi][ni], Al[mi], Bh[ni]);
                }
        }
        __syncthreads();
    }

    // ---- stage logits to smem (overlays A region) ----
    float* lsm = (float*)smem;
#pragma unroll
    for (int mi = 0; mi < 2; mi++)
#pragma unroll
        for (int ni = 0; ni < 4; ni++) {
            int r = wrow * 32 + mi * 16 + g;
            int c = wcol * 32 + ni * 8 + q * 2;
            lsm[r * LDL + c]           = acc[mi][ni][0];
            lsm[r * LDL + c + 1]       = acc[mi][ni][1];
            lsm[(r + 8) * LDL + c]     = acc[mi][ni][2];
            lsm[(r + 8) * LDL + c + 1] = acc[mi][ni][3];
        }

    __shared__ int hist[NE];
    if (tid < NE) hist[tid] = 0;
    __syncthreads();

    if (tid < MTILE) {
        const float* l = &lsm[tid * LDL];
        float mx = -3.0e38f;
#pragma unroll
        for (int e = 0; e < NE; ++e) mx = fmaxf(mx, l[e]);
        float Z = 0.f;
#pragma unroll
        for (int e = 0; e < NE; ++e) Z += expf(l[e] - mx);

        float m1 = -3.0e38f, m2 = -3.0e38f;
        int i1 = 0, i2 = 0;
#pragma unroll
        for (int e = 0; e < NE; ++e) {
            float v = l[e];
            if (v > m1) { m2 = m1; i2 = i1; m1 = v; i1 = e; }
            else if (v > m2) { m2 = v; i2 = e; }
        }
        float p1 = expf(m1 - mx) / Z;
        float p2 = expf(m2 - mx) / Z;
        float sN = p1 + p2 + 1e-8f;

        int n = row0 + tid;
        out[OFF_W + 2 * n]       = p1 / sN;
        out[OFF_W + 2 * n + 1]   = p2 / sN;
        out[OFF_IDX + 2 * n]     = (float)i1;
        out[OFF_IDX + 2 * n + 1] = (float)i2;
        g_flat[2 * n]     = i1;
        g_flat[2 * n + 1] = i2;
        atomicAdd(&hist[i1], 1);
        atomicAdd(&hist[i2], 1);
    }
    __syncthreads();
    if (tid < NE) g_bc[tid * NCTA + blockIdx.x] = hist[tid];
}

// ===================================================================
// Kernel 2: exclusive scan of g_bc (8192 values) + expert offsets
// ===================================================================
__global__ __launch_bounds__(1024) void scan_kernel(float* __restrict__ out) {
    __shared__ int wsum[32];
    const int t = threadIdx.x;
    const int lane = t & 31, w = t >> 5;

    int v[8], pre[8];
    int s = 0;
#pragma unroll
    for (int i = 0; i < 8; i++) { v[i] = g_bc[t * 8 + i]; pre[i] = s; s += v[i]; }

    int inc = s;
#pragma unroll
    for (int d = 1; d < 32; d <<= 1) {
        int o = __shfl_up_sync(0xffffffffu, inc, d);
        if (lane >= d) inc += o;
    }
    if (lane == 31) wsum[w] = inc;
    __syncthreads();
    if (w == 0) {
        int z = wsum[lane];
#pragma unroll
        for (int d = 1; d < 32; d <<= 1) {
            int o = __shfl_up_sync(0xffffffffu, z, d);
            if (lane >= d) z += o;
        }
        wsum[lane] = z;
    }
    __syncthreads();
    int base = (w > 0 ? wsum[w - 1] : 0) + (inc - s);

#pragma unroll
    for (int i = 0; i < 8; i++) {
        int j = t * 8 + i;
        g_off2[j] = base + pre[i];
        if ((j & (NCTA - 1)) == NCTA - 1)
            out[OFF_OFFS + (j >> 7)] = (float)(base + pre[i] + v[i]);
    }
    if (t == 0) { out[OFF_AUX] = 0.f; out[OFF_Z] = 0.f; }
}

// ===================================================================
// Kernel 3: stable placement -> gather_indices
// ===================================================================
__global__ __launch_bounds__(256) void place_kernel(float* __restrict__ out) {
    __shared__ int cnt[8][NE];
    const int t = threadIdx.x, blk = blockIdx.x;
    const int lane = t & 31, w = t >> 5;
    for (int i = t; i < 8 * NE; i += 256) ((int*)cnt)[i] = 0;
    __syncthreads();

    const int i = blk * 256 + t;
    const int e = g_flat[i];
    unsigned m = __match_any_sync(0xffffffffu, e);
    int r = __popc(m & ((1u << lane) - 1u));
    if (r == 0) cnt[w][e] = __popc(m);
    __syncthreads();

    int woff = 0;
#pragma unroll
    for (int ww = 0; ww < 8; ww++)
        if (ww < w) woff += cnt[ww][e];

    int pos = g_off2[e * NCTA + blk] + woff + r;
    out[OFF_GATHER + pos] = (float)i;
}

// ===================================================================
extern "C" void kernel_launch(void* const* d_in, const int* in_sizes, int n_in,
                              void* d_out, int out_size)
{
    const float* x = (const float*)d_in[0];
    const float* w = (const float*)d_in[1];
    float* out = (float*)d_out;

    cudaFuncSetAttribute(router_kernel, cudaFuncAttributeMaxDynamicSharedMemorySize, SM_TOTAL);

    wconv_kernel<<<(NE * HID) / 256, 256>>>(w);
    router_kernel<<<NCTA, 256, SM_TOTAL>>>(x, out);
    scan_kernel<<<1, 1024>>>(out);
    place_kernel<<<NCTA, 256>>>(out);
}

// round 5
// speedup vs baseline: 2.5516x; 1.0117x over previous
#include <cuda_runtime.h>
#include <cuda_bf16.h>
#include <cstdint>
#include <math.h>

// ---------------- problem constants ----------------
#define NT      16384
#define HID     4096
#define NE      64
#define NK      32768

#define OFF_W      0
#define OFF_IDX    32768
#define OFF_OFFS   65536
#define OFF_GATHER 65600
#define OFF_AUX    98368
#define OFF_Z      98369

// GEMM tiling
#define MTILE   64
#define KSPLIT  4
#define KPER    (HID / KSPLIT)      // 1024
#define KC      64                  // bf16 K per chunk
#define NCHUNK  (KPER / KC)         // 16
#define NMT     (NT / MTILE)        // 256 M-tiles
#define NBLK    (NMT * KSPLIT)      // 1024 CTAs
#define NCTA    128                 // metadata block count (epilogue/place)

// smem: padded rows, 64 bf16 + 8 pad = 72 bf16 = 144 bytes
#define RSTRIDE 144
#define A_BYTES (MTILE * RSTRIDE)   // 9216
#define B_BYTES (NE * RSTRIDE)      // 9216
#define SM_AHI  0
#define SM_ALO  (A_BYTES)
#define SM_BHI  (2 * A_BYTES)
#define SM_BLO  (2 * A_BYTES + B_BYTES)
#define SM_TOTAL (2 * A_BYTES + 2 * B_BYTES)   // 36864
#define LDL     68                  // logits smem stride (floats): 272B rows, 16B-aligned

// ---------------- device scratch ----------------
__device__ int g_flat[NK];
__device__ int g_bc[NE * NCTA];
__device__ int g_off2[NE * NCTA];
__device__ __align__(16) __nv_bfloat16 g_whi[NE * HID];
__device__ __align__(16) __nv_bfloat16 g_wlo[NE * HID];
__device__ __align__(16) float g_part[KSPLIT * NT * NE];   // 16 MB partial logits

__device__ __forceinline__ unsigned pack_bf2(__nv_bfloat16 a, __nv_bfloat16 b) {
    return (unsigned)__bfloat16_as_ushort(a) | ((unsigned)__bfloat16_as_ushort(b) << 16);
}

__device__ __forceinline__ void mma16816(float* d, const uint32_t* a, const uint32_t* b) {
    asm volatile(
        "mma.sync.aligned.m16n8k16.row.col.f32.bf16.bf16.f32 "
        "{%0,%1,%2,%3}, {%4,%5,%6,%7}, {%8,%9}, {%0,%1,%2,%3};"
        : "+f"(d[0]), "+f"(d[1]), "+f"(d[2]), "+f"(d[3])
        : "r"(a[0]), "r"(a[1]), "r"(a[2]), "r"(a[3]), "r"(b[0]), "r"(b[1]));
}

// ===================================================================
// Kernel 0: preconvert gate_w to bf16 hi/lo
// ===================================================================
__global__ __launch_bounds__(256) void wconv_kernel(const float* __restrict__ w) {
    int i = blockIdx.x * 256 + threadIdx.x;
    float v = w[i];
    __nv_bfloat16 h = __float2bfloat16_rn(v);
    g_whi[i] = h;
    g_wlo[i] = __float2bfloat16_rn(v - __bfloat162float(h));
}

// ===================================================================
// Kernel 1: HMMA router GEMM (bf16 split), split-K partials
// grid = 1024 CTAs x 256 threads (8 warps: 2 M x 4 N)
// ===================================================================
__global__ __launch_bounds__(256, 2) void router_kernel(const float* __restrict__ x)
{
    extern __shared__ __align__(16) char smem[];
    const int tid  = threadIdx.x;
    const int wid  = tid >> 5;
    const int lane = tid & 31;
    const int mt   = blockIdx.x >> 2;          // M-tile
    const int ksp  = blockIdx.x & 3;           // K split
    const int row0 = mt * MTILE;

    const int wrow = wid >> 2;                 // 0..1  (32-token group)
    const int wcol = wid & 3;                  // 0..3  (16-expert group)
    const int g = lane >> 2;
    const int q = lane & 3;

    // A: 64 rows x 16 float4 per chunk = 1024 units, 4/thread
    const float4* x4 = (const float4*)x;
    int a_r[4], a_c4[4];
#pragma unroll
    for (int i = 0; i < 4; i++) {
        int u = tid + 256 * i;
        a_r[i]  = u >> 4;
        a_c4[i] = u & 15;
    }
    // B: 64 rows x 8 float4 per split per chunk = 512 units, 2/thread
    int b_r[2], b_c16[2];
#pragma unroll
    for (int j = 0; j < 2; j++) {
        int u = tid + 256 * j;
        b_r[j]   = u >> 3;
        b_c16[j] = u & 7;
    }
    const float4* whi4 = (const float4*)g_whi;
    const float4* wlo4 = (const float4*)g_wlo;

    const int kaBase = ksp * (KPER / 4);       // float4 offset in x row
    const int kbBase = ksp * (KPER / 8);       // float4 offset in w row (bf16)

    // prefetch chunk 0
    float4 pa[4], pbh[2], pbl[2];
#pragma unroll
    for (int i = 0; i < 4; i++)
        pa[i] = x4[(size_t)(row0 + a_r[i]) * (HID / 4) + kaBase + a_c4[i]];
#pragma unroll
    for (int j = 0; j < 2; j++) {
        int gi = b_r[j] * (HID / 8) + kbBase + b_c16[j];
        pbh[j] = whi4[gi];
        pbl[j] = wlo4[gi];
    }

    float acc[2][2][4];
#pragma unroll
    for (int mi = 0; mi < 2; mi++)
#pragma unroll
        for (int ni = 0; ni < 2; ni++)
#pragma unroll
            for (int c = 0; c < 4; c++) acc[mi][ni][c] = 0.f;

#pragma unroll 1
    for (int s = 0; s < NCHUNK; ++s) {
        // commit prefetched chunk (convert A to hi/lo)
#pragma unroll
        for (int i = 0; i < 4; i++) {
            float4 v = pa[i];
            __nv_bfloat16 hx = __float2bfloat16_rn(v.x);
            __nv_bfloat16 hy = __float2bfloat16_rn(v.y);
            __nv_bfloat16 hz = __float2bfloat16_rn(v.z);
            __nv_bfloat16 hw = __float2bfloat16_rn(v.w);
            uint2 H, L;
            H.x = pack_bf2(hx, hy);
            H.y = pack_bf2(hz, hw);
            L.x = pack_bf2(__float2bfloat16_rn(v.x - __bfloat162float(hx)),
                           __float2bfloat16_rn(v.y - __bfloat162float(hy)));
            L.y = pack_bf2(__float2bfloat16_rn(v.z - __bfloat162float(hz)),
                           __float2bfloat16_rn(v.w - __bfloat162float(hw)));
            int off = a_r[i] * RSTRIDE + a_c4[i] * 8;
            *(uint2*)(smem + SM_AHI + off) = H;
            *(uint2*)(smem + SM_ALO + off) = L;
        }
#pragma unroll
        for (int j = 0; j < 2; j++) {
            int off = b_r[j] * RSTRIDE + b_c16[j] * 16;
            *(float4*)(smem + SM_BHI + off) = pbh[j];
            *(float4*)(smem + SM_BLO + off) = pbl[j];
        }
        __syncthreads();

        // prefetch next chunk
        if (s + 1 < NCHUNK) {
            const int ka = kaBase + (s + 1) * (KC / 4);
            const int kb = kbBase + (s + 1) * (KC / 8);
#pragma unroll
            for (int i = 0; i < 4; i++)
                pa[i] = x4[(size_t)(row0 + a_r[i]) * (HID / 4) + ka + a_c4[i]];
#pragma unroll
            for (int j = 0; j < 2; j++) {
                int gi = b_r[j] * (HID / 8) + kb + b_c16[j];
                pbh[j] = whi4[gi];
                pbl[j] = wlo4[gi];
            }
        }

        // compute: 4 k-steps of 16
#pragma unroll
        for (int ks = 0; ks < 4; ++ks) {
            const int k0 = ks * 16 + q * 2;
            uint32_t Ah[2][4], Al[2][4], Bh[2][2], Bl[2][2];
#pragma unroll
            for (int mi = 0; mi < 2; mi++) {
                int r = wrow * 32 + mi * 16 + g;
                int o00 = r * RSTRIDE + k0 * 2;
                int o10 = (r + 8) * RSTRIDE + k0 * 2;
                Ah[mi][0] = *(const uint32_t*)(smem + SM_AHI + o00);
                Ah[mi][1] = *(const uint32_t*)(smem + SM_AHI + o10);
                Ah[mi][2] = *(const uint32_t*)(smem + SM_AHI + o00 + 16);
                Ah[mi][3] = *(const uint32_t*)(smem + SM_AHI + o10 + 16);
                Al[mi][0] = *(const uint32_t*)(smem + SM_ALO + o00);
                Al[mi][1] = *(const uint32_t*)(smem + SM_ALO + o10);
                Al[mi][2] = *(const uint32_t*)(smem + SM_ALO + o00 + 16);
                Al[mi][3] = *(const uint32_t*)(smem + SM_ALO + o10 + 16);
            }
#pragma unroll
            for (int ni = 0; ni < 2; ni++) {
                int n = wcol * 16 + ni * 8 + g;
                int o = n * RSTRIDE + k0 * 2;
                Bh[ni][0] = *(const uint32_t*)(smem + SM_BHI + o);
                Bh[ni][1] = *(const uint32_t*)(smem + SM_BHI + o + 16);
                Bl[ni][0] = *(const uint32_t*)(smem + SM_BLO + o);
                Bl[ni][1] = *(const uint32_t*)(smem + SM_BLO + o + 16);
            }
#pragma unroll
            for (int mi = 0; mi < 2; mi++)
#pragma unroll
                for (int ni = 0; ni < 2; ni++) {
                    mma16816(acc[mi][ni], Ah[mi], Bh[ni]);
                    mma16816(acc[mi][ni], Ah[mi], Bl[ni]);
                    mma16816(acc[mi][ni], Al[mi], Bh[ni]);
                }
        }
        __syncthreads();
    }

    // stage logits to smem then coalesced store of partials
    float* lsm = (float*)smem;
#pragma unroll
    for (int mi = 0; mi < 2; mi++)
#pragma unroll
        for (int ni = 0; ni < 2; ni++) {
            int r = wrow * 32 + mi * 16 + g;
            int c = wcol * 16 + ni * 8 + q * 2;
            lsm[r * LDL + c]           = acc[mi][ni][0];
            lsm[r * LDL + c + 1]       = acc[mi][ni][1];
            lsm[(r + 8) * LDL + c]     = acc[mi][ni][2];
            lsm[(r + 8) * LDL + c + 1] = acc[mi][ni][3];
        }
    __syncthreads();

    // 256 threads write 64 tokens x 64 floats: token = tid>>2, quarter = tid&3
    {
        int tok = tid >> 2;
        int qo  = (tid & 3) * 16;
        float* gp = g_part + (size_t)ksp * NT * NE + (size_t)(row0 + tok) * NE + qo;
        const float* ls = &lsm[tok * LDL + qo];
#pragma unroll
        for (int v = 0; v < 4; v++)
            ((float4*)gp)[v] = *(const float4*)(ls + 4 * v);
    }
}

// ===================================================================
// Kernel 2: reduce partials + softmax + top2 + hist
// grid = 128 blocks x 128 threads (one token per thread)
// ===================================================================
__global__ __launch_bounds__(128) void epi_kernel(float* __restrict__ out)
{
    __shared__ int hist[NE];
    const int t = threadIdx.x;
    const int blk = blockIdx.x;
    const int n = blk * 128 + t;

    if (t < NE) hist[t] = 0;
    __syncthreads();

    float l[NE];
    {
        const float4* p0 = (const float4*)(g_part + (size_t)n * NE);
#pragma unroll
        for (int v = 0; v < 16; v++) {
            float4 a = p0[v];
            l[4*v] = a.x; l[4*v+1] = a.y; l[4*v+2] = a.z; l[4*v+3] = a.w;
        }
#pragma unroll
        for (int ks = 1; ks < KSPLIT; ks++) {
            const float4* p = (const float4*)(g_part + (size_t)ks * NT * NE + (size_t)n * NE);
#pragma unroll
            for (int v = 0; v < 16; v++) {
                float4 a = p[v];
                l[4*v] += a.x; l[4*v+1] += a.y; l[4*v+2] += a.z; l[4*v+3] += a.w;
            }
        }
    }

    float mx = -3.0e38f;
#pragma unroll
    for (int e = 0; e < NE; ++e) mx = fmaxf(mx, l[e]);
    float Z = 0.f;
#pragma unroll
    for (int e = 0; e < NE; ++e) Z += expf(l[e] - mx);

    float m1 = -3.0e38f, m2 = -3.0e38f;
    int i1 = 0, i2 = 0;
#pragma unroll
    for (int e = 0; e < NE; ++e) {
        float v = l[e];
        if (v > m1) { m2 = m1; i2 = i1; m1 = v; i1 = e; }
        else if (v > m2) { m2 = v; i2 = e; }
    }
    float p1 = expf(m1 - mx) / Z;
    float p2 = expf(m2 - mx) / Z;
    float sN = p1 + p2 + 1e-8f;

    out[OFF_W + 2 * n]       = p1 / sN;
    out[OFF_W + 2 * n + 1]   = p2 / sN;
    out[OFF_IDX + 2 * n]     = (float)i1;
    out[OFF_IDX + 2 * n + 1] = (float)i2;
    g_flat[2 * n]     = i1;
    g_flat[2 * n + 1] = i2;
    atomicAdd(&hist[i1], 1);
    atomicAdd(&hist[i2], 1);
    __syncthreads();
    if (t < NE) g_bc[t * NCTA + blk] = hist[t];
}

// ===================================================================
// Kernel 3: exclusive scan of g_bc (8192 values) + expert offsets
// ===================================================================
__global__ __launch_bounds__(1024) void scan_kernel(float* __restrict__ out) {
    __shared__ int wsum[32];
    const int t = threadIdx.x;
    const int lane = t & 31, w = t >> 5;

    int v[8], pre[8];
    int s = 0;
#pragma unroll
    for (int i = 0; i < 8; i++) { v[i] = g_bc[t * 8 + i]; pre[i] = s; s += v[i]; }

    int inc = s;
#pragma unroll
    for (int d = 1; d < 32; d <<= 1) {
        int o = __shfl_up_sync(0xffffffffu, inc, d);
        if (lane >= d) inc += o;
    }
    if (lane == 31) wsum[w] = inc;
    __syncthreads();
    if (w == 0) {
        int z = wsum[lane];
#pragma unroll
        for (int d = 1; d < 32; d <<= 1) {
            int o = __shfl_up_sync(0xffffffffu, z, d);
            if (lane >= d) z += o;
        }
        wsum[lane] = z;
    }
    __syncthreads();
    int base = (w > 0 ? wsum[w - 1] : 0) + (inc - s);

#pragma unroll
    for (int i = 0; i < 8; i++) {
        int j = t * 8 + i;
        g_off2[j] = base + pre[i];
        if ((j & (NCTA - 1)) == NCTA - 1)
            out[OFF_OFFS + (j >> 7)] = (float)(base + pre[i] + v[i]);
    }
    if (t == 0) { out[OFF_AUX] = 0.f; out[OFF_Z] = 0.f; }
}

// ===================================================================
// Kernel 4: stable placement -> gather_indices
// ===================================================================
__global__ __launch_bounds__(256) void place_kernel(float* __restrict__ out) {
    __shared__ int cnt[8][NE];
    const int t = threadIdx.x, blk = blockIdx.x;
    const int lane = t & 31, w = t >> 5;
    for (int i = t; i < 8 * NE; i += 256) ((int*)cnt)[i] = 0;
    __syncthreads();

    const int i = blk * 256 + t;
    const int e = g_flat[i];
    unsigned m = __match_any_sync(0xffffffffu, e);
    int r = __popc(m & ((1u << lane) - 1u));
    if (r == 0) cnt[w][e] = __popc(m);
    __syncthreads();

    int woff = 0;
#pragma unroll
    for (int ww = 0; ww < 8; ww++)
        if (ww < w) woff += cnt[ww][e];

    int pos = g_off2[e * NCTA + blk] + woff + r;
    out[OFF_GATHER + pos] = (float)i;
}

// ===================================================================
extern "C" void kernel_launch(void* const* d_in, const int* in_sizes, int n_in,
                              void* d_out, int out_size)
{
    const float* x = (const float*)d_in[0];
    const float* w = (const float*)d_in[1];
    float* out = (float*)d_out;

    cudaFuncSetAttribute(router_kernel, cudaFuncAttributeMaxDynamicSharedMemorySize, SM_TOTAL);

    wconv_kernel<<<(NE * HID) / 256, 256>>>(w);
    router_kernel<<<NBLK, 256, SM_TOTAL>>>(x);
    epi_kernel<<<NCTA, 128>>>(out);
    scan_kernel<<<1, 1024>>>(out);
    place_kernel<<<NCTA, 256>>>(out);
}